// round 2
// baseline (speedup 1.0000x reference)
#include <cuda_runtime.h>
#include <math.h>

// Problem constants
#define M_    100
#define C_    30
#define D_    300
#define K_    3
#define MC    3000          // M_*C_
#define MM    10000         // M_*M_

// ---------------- scratch (device globals; no allocs allowed) ----------------
static __device__ float d_f   [M_*D_];        // tanh(fmc_in @ W + b)
static __device__ float d_g   [M_*D_];        // f @ B^T
static __device__ float d_psi [M_*C_];
static __device__ float d_ER  [K_*MC*D_];     // ent @ R_k        (2.7M floats)
static __device__ float d_fD  [K_*M_*D_];
static __device__ float d_s   [K_*M_*M_];
static __device__ float d_a   [M_*M_*K_];
static __device__ float d_phi [M_*M_*C_*C_];  // 9M floats = 36 MB
static __device__ float d_mbarA[M_*M_*C_];
static __device__ float d_mbarB[M_*M_*C_];
static __device__ float d_t   [M_*C_];        // psi + stot

// ---------------- generic tiled SGEMM (NN), 64x64x16, 256 thr, 4x4 micro ----
// C[m,n] = sum_k A[m,k] * B[k,n]; optional epilogue tanh(x + bias[n])
template<int EPI>
__global__ void sgemm_nn(const float* __restrict__ A, const float* __restrict__ B,
                         float* __restrict__ C, int M, int N, int K,
                         long sA, long sB, long sC, const float* __restrict__ bias)
{
    A += (long)blockIdx.z * sA;
    B += (long)blockIdx.z * sB;
    C += (long)blockIdx.z * sC;
    __shared__ float As[16][64];
    __shared__ float Bs[16][64];
    const int tid  = threadIdx.x;
    const int row0 = blockIdx.y * 64;
    const int col0 = blockIdx.x * 64;
    const int tm = (tid >> 4) * 4;       // 0..60
    const int tn = (tid & 15) * 4;       // 0..60
    float acc[4][4] = {};

    for (int k0 = 0; k0 < K; k0 += 16) {
        #pragma unroll
        for (int i = 0; i < 4; i++) {
            int idx = tid + i * 256;                  // 1024 = 64x16
            int m = idx >> 4, kk = idx & 15;
            int gr = row0 + m, gc = k0 + kk;
            As[kk][m] = (gr < M && gc < K) ? A[(long)gr * K + gc] : 0.f;
        }
        #pragma unroll
        for (int i = 0; i < 4; i++) {
            int idx = tid + i * 256;                  // 1024 = 16x64
            int kk = idx >> 6, n = idx & 63;
            int gr = k0 + kk, gc = col0 + n;
            Bs[kk][n] = (gr < K && gc < N) ? B[(long)gr * N + gc] : 0.f;
        }
        __syncthreads();
        #pragma unroll
        for (int kk = 0; kk < 16; kk++) {
            float a4[4], b4[4];
            #pragma unroll
            for (int x = 0; x < 4; x++) a4[x] = As[kk][tm + x];
            #pragma unroll
            for (int y = 0; y < 4; y++) b4[y] = Bs[kk][tn + y];
            #pragma unroll
            for (int x = 0; x < 4; x++)
                #pragma unroll
                for (int y = 0; y < 4; y++)
                    acc[x][y] += a4[x] * b4[y];
        }
        __syncthreads();
    }
    #pragma unroll
    for (int x = 0; x < 4; x++) {
        int r = row0 + tm + x;
        if (r >= M) continue;
        #pragma unroll
        for (int y = 0; y < 4; y++) {
            int c = col0 + tn + y;
            if (c >= N) continue;
            float v = acc[x][y];
            if (EPI == 1) v = tanhf(v + bias[c]);
            C[(long)r * N + c] = v;
        }
    }
}

// ---------------- generic tiled SGEMM (NT): C[m,n] = sum_k A[m,k]*B[n,k] ----
__global__ void sgemm_nt(const float* __restrict__ A, const float* __restrict__ B,
                         float* __restrict__ C, int M, int N, int K,
                         long sA, long sB, long sC)
{
    A += (long)blockIdx.z * sA;
    B += (long)blockIdx.z * sB;
    C += (long)blockIdx.z * sC;
    __shared__ float As[16][64];
    __shared__ float Bs[16][64];
    const int tid  = threadIdx.x;
    const int row0 = blockIdx.y * 64;
    const int col0 = blockIdx.x * 64;
    const int tm = (tid >> 4) * 4;
    const int tn = (tid & 15) * 4;
    float acc[4][4] = {};

    for (int k0 = 0; k0 < K; k0 += 16) {
        #pragma unroll
        for (int i = 0; i < 4; i++) {
            int idx = tid + i * 256;
            int m = idx >> 4, kk = idx & 15;
            int gr = row0 + m, gc = k0 + kk;
            As[kk][m] = (gr < M && gc < K) ? A[(long)gr * K + gc] : 0.f;
        }
        #pragma unroll
        for (int i = 0; i < 4; i++) {
            int idx = tid + i * 256;
            int n = idx >> 4, kk = idx & 15;
            int gr = col0 + n, gc = k0 + kk;
            Bs[kk][n] = (gr < N && gc < K) ? B[(long)gr * K + gc] : 0.f;
        }
        __syncthreads();
        #pragma unroll
        for (int kk = 0; kk < 16; kk++) {
            float a4[4], b4[4];
            #pragma unroll
            for (int x = 0; x < 4; x++) a4[x] = As[kk][tm + x];
            #pragma unroll
            for (int y = 0; y < 4; y++) b4[y] = Bs[kk][tn + y];
            #pragma unroll
            for (int x = 0; x < 4; x++)
                #pragma unroll
                for (int y = 0; y < 4; y++)
                    acc[x][y] += a4[x] * b4[y];
        }
        __syncthreads();
    }
    #pragma unroll
    for (int x = 0; x < 4; x++) {
        int r = row0 + tm + x;
        if (r >= M) continue;
        #pragma unroll
        for (int y = 0; y < 4; y++) {
            int c = col0 + tn + y;
            if (c >= N) continue;
            C[(long)r * N + c] = acc[x][y];
        }
    }
}

// ---------------- psi[m,c] = sum_d ent[m,c,d] * g[m,d] ----------------------
__global__ void psi_kernel(const float* __restrict__ ent)
{
    int m = blockIdx.x;
    __shared__ float gs[D_];
    for (int d = threadIdx.x; d < D_; d += blockDim.x) gs[d] = d_g[m * D_ + d];
    __syncthreads();
    int w = threadIdx.x >> 5, lane = threadIdx.x & 31;
    for (int c = w; c < C_; c += (blockDim.x >> 5)) {
        const float* e = ent + ((long)m * C_ + c) * D_;
        float s = 0.f;
        for (int d = lane; d < D_; d += 32) s += e[d] * gs[d];
        #pragma unroll
        for (int o = 16; o; o >>= 1) s += __shfl_down_sync(0xffffffffu, s, o);
        if (lane == 0) d_psi[m * C_ + c] = s;
    }
}

// ---------------- a[i,j,k] = softmax_k( s_k[i,j] / sqrt(D) ) ----------------
__global__ void a_kernel()
{
    int ij = blockIdx.x * blockDim.x + threadIdx.x;
    if (ij >= MM) return;
    const float scale = 0.05773502691896258f;  // 1/sqrt(300)
    float s0 = d_s[0 * MM + ij] * scale;
    float s1 = d_s[1 * MM + ij] * scale;
    float s2 = d_s[2 * MM + ij] * scale;
    float mx = fmaxf(s0, fmaxf(s1, s2));
    float e0 = expf(s0 - mx), e1 = expf(s1 - mx), e2 = expf(s2 - mx);
    float inv = 1.f / (e0 + e1 + e2);
    d_a[ij * 3 + 0] = e0 * inv;
    d_a[ij * 3 + 1] = e1 * inv;
    d_a[ij * 3 + 2] = e2 * inv;
}

// ---------------- phi GEMM: 3 fused NT GEMMs + a-weighted epilogue ----------
// acc_k[ip, jq] = sum_e ent[ip,e] * ER_k[jq,e];  phi = sum_k a[i,j,k]*acc_k
__global__ void phi_gemm(const float* __restrict__ A)   // A = ent [3000 x 300]
{
    __shared__ float As[16][64];
    __shared__ float Bs[3][16][64];
    const int tid  = threadIdx.x;
    const int row0 = blockIdx.y * 64;
    const int col0 = blockIdx.x * 64;
    const int tm = (tid >> 4) * 4;
    const int tn = (tid & 15) * 4;
    float acc[3][4][4] = {};

    for (int k0 = 0; k0 < D_; k0 += 16) {
        #pragma unroll
        for (int i = 0; i < 4; i++) {
            int idx = tid + i * 256;
            int m = idx >> 4, kk = idx & 15;
            int gr = row0 + m, gc = k0 + kk;
            As[kk][m] = (gr < MC && gc < D_) ? A[(long)gr * D_ + gc] : 0.f;
        }
        #pragma unroll
        for (int kb = 0; kb < 3; kb++) {
            #pragma unroll
            for (int i = 0; i < 4; i++) {
                int idx = tid + i * 256;
                int n = idx >> 4, kk = idx & 15;
                int gr = col0 + n, gc = k0 + kk;
                Bs[kb][kk][n] = (gr < MC && gc < D_)
                              ? d_ER[(long)kb * (MC * D_) + (long)gr * D_ + gc] : 0.f;
            }
        }
        __syncthreads();
        #pragma unroll
        for (int kk = 0; kk < 16; kk++) {
            float a4[4], b0[4], b1[4], b2[4];
            #pragma unroll
            for (int x = 0; x < 4; x++) a4[x] = As[kk][tm + x];
            #pragma unroll
            for (int y = 0; y < 4; y++) {
                b0[y] = Bs[0][kk][tn + y];
                b1[y] = Bs[1][kk][tn + y];
                b2[y] = Bs[2][kk][tn + y];
            }
            #pragma unroll
            for (int x = 0; x < 4; x++)
                #pragma unroll
                for (int y = 0; y < 4; y++) {
                    acc[0][x][y] += a4[x] * b0[y];
                    acc[1][x][y] += a4[x] * b1[y];
                    acc[2][x][y] += a4[x] * b2[y];
                }
        }
        __syncthreads();
    }
    // epilogue: combine with a[i,j,k]; scatter to phi[i,j,p,q]
    #pragma unroll
    for (int x = 0; x < 4; x++) {
        int r = row0 + tm + x;
        if (r >= MC) continue;
        int i = r / C_, p = r % C_;
        #pragma unroll
        for (int y = 0; y < 4; y++) {
            int c = col0 + tn + y;
            if (c >= MC) continue;
            int j = c / C_, q = c % C_;
            const float* aw = d_a + (i * M_ + j) * 3;
            float v = acc[0][x][y] * aw[0] + acc[1][x][y] * aw[1] + acc[2][x][y] * aw[2];
            d_phi[(long)(i * M_ + j) * (C_ * C_) + p * C_ + q] = v;
        }
    }
}

// ---------------- LBP ----------------
__global__ void zero_kernel()
{
    int idx = blockIdx.x * blockDim.x + threadIdx.x;
    if (idx < M_ * M_ * C_) d_mbarA[idx] = 0.f;
}

// t[i,p] = psi[i,p] + sum_j mbar[j,i,p]
__global__ void t_kernel(const float* __restrict__ mbar)
{
    int i = blockIdx.x;
    int p = threadIdx.x;
    if (p >= C_) return;
    float s = 0.f;
    for (int j = 0; j < M_; j++) s += mbar[(j * M_ + i) * C_ + p];
    d_t[i * C_ + p] = d_psi[i * C_ + p] + s;
}

// per (i,j): mval[q] = max(0, max_p(t[i,p]-mbar[j,i,p]+phi[i,j,p,q]))
// mbarN[i,j,q] = log(0.5*exp(mbar[i,j,q]) + 0.5*softmax_q(mval))
__global__ void lbp_update(const float* __restrict__ mbar, float* __restrict__ mbarN)
{
    const int w    = threadIdx.x >> 5;
    const int lane = threadIdx.x & 31;
    const int ij   = blockIdx.x * 8 + w;
    const int i = ij / M_, j = ij % M_;
    __shared__ float tt[8][32];

    if (lane < C_)
        tt[w][lane] = d_t[i * C_ + lane] - mbar[(j * M_ + i) * C_ + lane];
    __syncwarp();

    const float* ph = d_phi + (long)ij * (C_ * C_);
    float mv = -1e30f;
    if (lane < C_) {
        #pragma unroll 6
        for (int p = 0; p < C_; p++)
            mv = fmaxf(mv, tt[w][p] + ph[p * C_ + lane]);
        mv = fmaxf(mv, 0.f);
    }
    // softmax over lanes 0..29
    float z = (lane < C_) ? mv : -1e30f;
    float mx = z;
    #pragma unroll
    for (int o = 16; o; o >>= 1) mx = fmaxf(mx, __shfl_xor_sync(0xffffffffu, mx, o));
    float e = (lane < C_) ? expf(mv - mx) : 0.f;
    float sum = e;
    #pragma unroll
    for (int o = 16; o; o >>= 1) sum += __shfl_xor_sync(0xffffffffu, sum, o);
    if (lane < C_) {
        float sm  = e / sum;
        float old = mbar[ij * C_ + lane];
        mbarN[ij * C_ + lane] = logf(0.5f * expf(old) + 0.5f * sm);
    }
}

// out[i,:] = softmax_q( psi[i,q] + sum_j mbar[j,i,q] - mbar[i,i,q] )
__global__ void final_kernel(float* __restrict__ out, const float* __restrict__ mbar)
{
    int i = blockIdx.x;
    int lane = threadIdx.x;
    float u = -1e30f;
    if (lane < C_) {
        float s = 0.f;
        for (int j = 0; j < M_; j++) s += mbar[(j * M_ + i) * C_ + lane];
        s -= mbar[(i * M_ + i) * C_ + lane];
        u = d_psi[i * C_ + lane] + s;
    }
    float mx = u;
    #pragma unroll
    for (int o = 16; o; o >>= 1) mx = fmaxf(mx, __shfl_xor_sync(0xffffffffu, mx, o));
    float e = (lane < C_) ? expf(u - mx) : 0.f;
    float sum = e;
    #pragma unroll
    for (int o = 16; o; o >>= 1) sum += __shfl_xor_sync(0xffffffffu, sum, o);
    if (lane < C_) out[i * C_ + lane] = e / sum;
}

// ---------------- host ----------------
extern "C" void kernel_launch(void* const* d_in, const int* in_sizes, int n_in,
                              void* d_out, int out_size)
{
    const float* ent    = (const float*)d_in[0];   // [100,30,300]
    const float* fmc_in = (const float*)d_in[1];   // [100,900]
    const float* W_fmc  = (const float*)d_in[2];   // [900,300]
    const float* b_fmc  = (const float*)d_in[3];   // [300]
    const float* Bmat   = (const float*)d_in[4];   // [300,300]
    const float* Rmat   = (const float*)d_in[5];   // [3,300,300]
    const float* Dmat   = (const float*)d_in[6];   // [3,300,300]
    float* out = (float*)d_out;

    float *pf, *pg, *pER, *pfD, *ps, *pmA, *pmB;
    cudaGetSymbolAddress((void**)&pf,  d_f);
    cudaGetSymbolAddress((void**)&pg,  d_g);
    cudaGetSymbolAddress((void**)&pER, d_ER);
    cudaGetSymbolAddress((void**)&pfD, d_fD);
    cudaGetSymbolAddress((void**)&ps,  d_s);
    cudaGetSymbolAddress((void**)&pmA, d_mbarA);
    cudaGetSymbolAddress((void**)&pmB, d_mbarB);

    // f = tanh(fmc_in @ W_fmc + b)              [100 x 300 x 900]
    sgemm_nn<1><<<dim3(5, 2, 1), 256>>>(fmc_in, W_fmc, pf, 100, 300, 900, 0, 0, 0, b_fmc);
    // g = f @ B^T                                [100 x 300 x 300]
    sgemm_nt<<<dim3(5, 2, 1), 256>>>(pf, Bmat, pg, 100, 300, 300, 0, 0, 0);
    // psi
    psi_kernel<<<100, 256>>>(ent);
    // ER_k = ent @ R_k   (batched k)             [3000 x 300 x 300] x3
    sgemm_nn<0><<<dim3(5, 47, 3), 256>>>(ent, Rmat, pER, 3000, 300, 300,
                                         0, 90000, 900000, nullptr);
    // fD_k = f @ D_k     (batched k)             [100 x 300 x 300] x3
    sgemm_nn<0><<<dim3(5, 2, 3), 256>>>(pf, Dmat, pfD, 100, 300, 300,
                                        0, 90000, 30000, nullptr);
    // s_k = fD_k @ f^T   (batched k)             [100 x 100 x 300] x3
    sgemm_nt<<<dim3(2, 2, 3), 256>>>(pfD, pf, ps, 100, 100, 300,
                                     30000, 0, 10000);
    // a = softmax_k(s / sqrt(D))
    a_kernel<<<40, 256>>>();
    // phi (the big one: 16.2 GF fp32)
    phi_gemm<<<dim3(47, 47), 256>>>(ent);

    // LBP: mbar0 = 0; 10 damped iterations (ping-pong A<->B)
    zero_kernel<<<(M_ * M_ * C_ + 255) / 256, 256>>>();
    for (int it = 0; it < 10; it++) {
        const float* src = (it & 1) ? pmB : pmA;
        float*       dst = (it & 1) ? pmA : pmB;
        t_kernel<<<100, 32>>>(src);
        lbp_update<<<1250, 256>>>(src, dst);
    }
    // after 10 iters the live buffer is A (last write: it=9, dst=A)
    final_kernel<<<100, 32>>>(out, pmA);
}

// round 4
// speedup vs baseline: 2.4411x; 2.4411x over previous
#include <cuda_runtime.h>
#include <cstdint>
#include <math.h>

#define M_    100
#define C_    30
#define D_    300
#define K_    3
#define MC    3000
#define MM    10000
#define KPAD  320            // padded K dim (20 chunks of 16)
#define RPAD  3072           // padded MC rows
#define NPAD  384            // padded rows for R^T
#define NCH   20             // K chunks of 16

// ---------------- scratch ----------------
static __device__ float d_f   [M_*D_];
static __device__ float d_g   [M_*D_];
static __device__ float d_psi [M_*C_];
static __device__ float d_fD  [K_*M_*D_];
static __device__ float d_s   [K_*M_*M_];
static __device__ float d_a   [M_*M_*K_];
static __device__ float d_Apad[RPAD*KPAD];        // ent, tf32-rounded, padded
static __device__ float d_Bpad[K_*RPAD*KPAD];     // ER_k, tf32, padded
static __device__ float d_Rt  [K_*NPAD*KPAD];     // R_k^T, tf32, padded
static __device__ float d_phi [MC*MC];            // 36 MB, [ip][jq]
static __device__ float d_mbarA[M_*M_*C_];
static __device__ float d_mbarB[M_*M_*C_];
static __device__ float d_t   [M_*C_];

// ---------------- helpers ----------------
__device__ __forceinline__ uint32_t smem_u32(const void* p) {
    uint32_t a;
    asm("{ .reg .u64 t; cvta.to.shared.u64 t, %1; cvt.u32.u64 %0, t; }" : "=r"(a) : "l"(p));
    return a;
}
__device__ __forceinline__ float to_tf32(float x) {
    float r; asm("cvt.rna.tf32.f32 %0, %1;" : "=f"(r) : "f"(x)); return r;
}
__device__ __forceinline__ void cpasync16(uint32_t dst, const void* src) {
    asm volatile("{\n\t.reg .u64 g;\n\tcvta.to.global.u64 g, %1;\n\t"
                 "cp.async.cg.shared.global [%0], [g], 16;\n\t}"
                 :: "r"(dst), "l"(src));
}
#define CP_COMMIT() asm volatile("cp.async.commit_group;" ::: "memory")
#define CP_WAIT(n)  asm volatile("cp.async.wait_group %0;" :: "n"(n) : "memory")

__device__ __forceinline__ void mma_tf32(float* c, const uint32_t* a, const uint32_t* b) {
    asm volatile("mma.sync.aligned.m16n8k8.row.col.f32.tf32.tf32.f32 "
        "{%0,%1,%2,%3}, {%4,%5,%6,%7}, {%8,%9}, {%0,%1,%2,%3};"
        : "+f"(c[0]), "+f"(c[1]), "+f"(c[2]), "+f"(c[3])
        : "r"(a[0]), "r"(a[1]), "r"(a[2]), "r"(a[3]), "r"(b[0]), "r"(b[1]));
}

// ---------------- pack kernels ----------------
__global__ void pack_A(const float* __restrict__ ent) {
    int idx = blockIdx.x * blockDim.x + threadIdx.x;
    if (idx >= RPAD * KPAD) return;
    int r = idx / KPAD, d = idx - r * KPAD;
    d_Apad[idx] = (r < MC && d < D_) ? to_tf32(ent[r * D_ + d]) : 0.f;
}
__global__ void pack_Rt(const float* __restrict__ R) {
    int idx = blockIdx.x * blockDim.x + threadIdx.x;
    if (idx >= K_ * NPAD * KPAD) return;
    int k = idx / (NPAD * KPAD);
    int rem = idx - k * (NPAD * KPAD);
    int n = rem / KPAD, d = rem - n * KPAD;
    d_Rt[idx] = (n < D_ && d < D_) ? to_tf32(R[k * D_ * D_ + d * D_ + n]) : 0.f;
}

// ================= ER via mma.sync tf32 ==============================
// ER_k[jq][e] = sum_d Apad[jq][d] * Rt_k[e][d]   (NT, row.col mma)
// CTA 128x64, 8 warps 4x2, warp 32x32. grid (5 ntiles, 24 mtiles, 3 k)
#define ER_BUF 3840   // words per buffer: A 128*20 + B 64*20
__global__ void __launch_bounds__(256) er_mma() {
    extern __shared__ uint32_t sm[];
    const int tid = threadIdx.x, lane = tid & 31, wid = tid >> 5;
    const int warpM = wid & 3, warpN = wid >> 2;
    const int row0 = blockIdx.y * 128;
    const int n0   = blockIdx.x * 64;
    const uint32_t smb = smem_u32(sm);
    const float4* Ag = (const float4*)(d_Apad + (size_t)row0 * KPAD);
    const float4* Bg = (const float4*)(d_Rt + (size_t)blockIdx.z * NPAD * KPAD
                                       + (size_t)n0 * KPAD);
    float acc[2][4][4] = {};

    auto prefetch = [&](int ch, int buf) {
        int c4o = ch * 4;
        uint32_t base = smb + buf * ER_BUF * 4;
        // A: 128 rows x 4 float4 = 512; 2 per thread
        #pragma unroll
        for (int it = 0; it < 2; it++) {
            int idx = tid + it * 256;
            int m = idx >> 2, q = idx & 3;
            cpasync16(base + (m * 20 + q * 4) * 4, Ag + m * 80 + c4o + q);
        }
        // B: 64 rows x 4 float4 = 256; 1 per thread
        {
            int n = tid >> 2, q = tid & 3;
            cpasync16(base + (2560 + n * 20 + q * 4) * 4, Bg + n * 80 + c4o + q);
        }
    };

    prefetch(0, 0);
    CP_COMMIT();
    for (int ch = 0; ch < NCH; ch++) {
        if (ch + 1 < NCH) { prefetch(ch + 1, (ch + 1) & 1); CP_COMMIT(); CP_WAIT(1); }
        else CP_WAIT(0);
        __syncthreads();
        const uint32_t* As = sm + (ch & 1) * ER_BUF;
        const uint32_t* Bs = As + 2560;
        #pragma unroll
        for (int ks = 0; ks < 2; ks++) {
            uint32_t af[2][4];
            #pragma unroll
            for (int mf = 0; mf < 2; mf++) {
                int r = warpM * 32 + mf * 16 + (lane >> 2);
                int c = ks * 8 + (lane & 3);
                af[mf][0] = As[r * 20 + c];
                af[mf][1] = As[(r + 8) * 20 + c];
                af[mf][2] = As[r * 20 + c + 4];
                af[mf][3] = As[(r + 8) * 20 + c + 4];
            }
            uint32_t bf[4][2];
            #pragma unroll
            for (int nf = 0; nf < 4; nf++) {
                int n = warpN * 32 + nf * 8 + (lane >> 2);
                int kk = ks * 8 + (lane & 3);
                bf[nf][0] = Bs[n * 20 + kk];
                bf[nf][1] = Bs[n * 20 + kk + 4];
            }
            #pragma unroll
            for (int mf = 0; mf < 2; mf++)
                #pragma unroll
                for (int nf = 0; nf < 4; nf++)
                    mma_tf32(acc[mf][nf], af[mf], bf[nf]);
        }
        __syncthreads();
    }

    // epilogue: tf32-round, store [jq][e] rows into Bpad (all in-range)
    float* Bout = d_Bpad + (size_t)blockIdx.z * RPAD * KPAD;
    #pragma unroll
    for (int mf = 0; mf < 2; mf++) {
        int r = row0 + warpM * 32 + mf * 16 + (lane >> 2);
        #pragma unroll
        for (int nf = 0; nf < 4; nf++) {
            int c = n0 + warpN * 32 + nf * 8 + (lane & 3) * 2;
            float2 v0 = make_float2(to_tf32(acc[mf][nf][0]), to_tf32(acc[mf][nf][1]));
            float2 v1 = make_float2(to_tf32(acc[mf][nf][2]), to_tf32(acc[mf][nf][3]));
            *(float2*)(Bout + (size_t)r * KPAD + c)       = v0;
            *(float2*)(Bout + (size_t)(r + 8) * KPAD + c) = v1;
        }
    }
}

// ================= phi via mma.sync tf32, 3 fused kinds ==============
// acc_k[ip][jq] = sum_e Apad[ip][e]*Bpad_k[jq][e];  phi = sum_k a[i,j,k]*acc_k
// CTA 128x64, 8 warps 4x2, warp 32x32 x3 kinds. grid (47 ctiles, 24 rtiles)
#define PHI_BUF 6400  // words: A 128*20 + 3x B 64*20
__global__ void __launch_bounds__(256) phi_mma() {
    extern __shared__ uint32_t sm[];
    const int tid = threadIdx.x, lane = tid & 31, wid = tid >> 5;
    const int warpM = wid & 3, warpN = wid >> 2;
    const int row0 = blockIdx.y * 128;
    const int col0 = blockIdx.x * 64;
    const uint32_t smb = smem_u32(sm);
    const float4* Ag = (const float4*)(d_Apad + (size_t)row0 * KPAD);
    float acc[3][2][4][4] = {};

    auto prefetch = [&](int ch, int buf) {
        int c4o = ch * 4;
        uint32_t base = smb + buf * PHI_BUF * 4;
        #pragma unroll
        for (int it = 0; it < 2; it++) {
            int idx = tid + it * 256;
            int m = idx >> 2, q = idx & 3;
            cpasync16(base + (m * 20 + q * 4) * 4, Ag + m * 80 + c4o + q);
        }
        #pragma unroll
        for (int it = 0; it < 3; it++) {
            int idx = tid + it * 256;
            int kb = idx >> 8, rem = idx & 255;
            int n = rem >> 2, q = rem & 3;
            const float4* Bg = (const float4*)(d_Bpad + (size_t)kb * RPAD * KPAD
                                               + (size_t)col0 * KPAD);
            cpasync16(base + (2560 + kb * 1280 + n * 20 + q * 4) * 4,
                      Bg + n * 80 + c4o + q);
        }
    };

    prefetch(0, 0);
    CP_COMMIT();
    for (int ch = 0; ch < NCH; ch++) {
        if (ch + 1 < NCH) { prefetch(ch + 1, (ch + 1) & 1); CP_COMMIT(); CP_WAIT(1); }
        else CP_WAIT(0);
        __syncthreads();
        const uint32_t* As = sm + (ch & 1) * PHI_BUF;
        #pragma unroll
        for (int ks = 0; ks < 2; ks++) {
            uint32_t af[2][4];
            #pragma unroll
            for (int mf = 0; mf < 2; mf++) {
                int r = warpM * 32 + mf * 16 + (lane >> 2);
                int c = ks * 8 + (lane & 3);
                af[mf][0] = As[r * 20 + c];
                af[mf][1] = As[(r + 8) * 20 + c];
                af[mf][2] = As[r * 20 + c + 4];
                af[mf][3] = As[(r + 8) * 20 + c + 4];
            }
            #pragma unroll
            for (int kb = 0; kb < 3; kb++) {
                const uint32_t* Bs = As + 2560 + kb * 1280;
                uint32_t bf[4][2];
                #pragma unroll
                for (int nf = 0; nf < 4; nf++) {
                    int n = warpN * 32 + nf * 8 + (lane >> 2);
                    int kk = ks * 8 + (lane & 3);
                    bf[nf][0] = Bs[n * 20 + kk];
                    bf[nf][1] = Bs[n * 20 + kk + 4];
                }
                #pragma unroll
                for (int mf = 0; mf < 2; mf++)
                    #pragma unroll
                    for (int nf = 0; nf < 4; nf++)
                        mma_tf32(acc[kb][mf][nf], af[mf], bf[nf]);
            }
        }
        __syncthreads();
    }

    // epilogue: combine kinds with a[i,j,k]; float2 stores into phi[ip][jq]
    #pragma unroll
    for (int mf = 0; mf < 2; mf++) {
        #pragma unroll
        for (int half = 0; half < 2; half++) {
            int r = row0 + warpM * 32 + mf * 16 + (lane >> 2) + half * 8;
            if (r >= MC) continue;
            int i = r / C_;
            #pragma unroll
            for (int nf = 0; nf < 4; nf++) {
                int c = col0 + warpN * 32 + nf * 8 + (lane & 3) * 2;
                if (c >= MC) continue;
                int j = c / C_;
                const float* aw = d_a + (i * M_ + j) * 3;
                float w0 = aw[0], w1 = aw[1], w2 = aw[2];
                int e0 = half * 2;          // regs 0,1 (half=0) or 2,3 (half=1)
                float v0 = acc[0][mf][nf][e0]     * w0 + acc[1][mf][nf][e0]     * w1
                         + acc[2][mf][nf][e0]     * w2;
                float v1 = acc[0][mf][nf][e0 + 1] * w0 + acc[1][mf][nf][e0 + 1] * w1
                         + acc[2][mf][nf][e0 + 1] * w2;
                *(float2*)(d_phi + (size_t)r * MC + c) = make_float2(v0, v1);
            }
        }
    }
}

// ---------------- small fp32 GEMMs ----------------
template<int EPI>
__global__ void sgemm_nn(const float* __restrict__ A, const float* __restrict__ B,
                         float* __restrict__ C, int M, int N, int K,
                         long sA, long sB, long sC, const float* __restrict__ bias)
{
    A += (long)blockIdx.z * sA;  B += (long)blockIdx.z * sB;  C += (long)blockIdx.z * sC;
    __shared__ float As[16][64];
    __shared__ float Bs[16][64];
    const int tid = threadIdx.x;
    const int row0 = blockIdx.y * 64, col0 = blockIdx.x * 64;
    const int tm = (tid >> 4) * 4, tn = (tid & 15) * 4;
    float acc[4][4] = {};
    for (int k0 = 0; k0 < K; k0 += 16) {
        #pragma unroll
        for (int i = 0; i < 4; i++) {
            int idx = tid + i * 256;
            int m = idx >> 4, kk = idx & 15;
            int gr = row0 + m, gc = k0 + kk;
            As[kk][m] = (gr < M && gc < K) ? A[(long)gr * K + gc] : 0.f;
        }
        #pragma unroll
        for (int i = 0; i < 4; i++) {
            int idx = tid + i * 256;
            int kk = idx >> 6, n = idx & 63;
            int gr = k0 + kk, gc = col0 + n;
            Bs[kk][n] = (gr < K && gc < N) ? B[(long)gr * N + gc] : 0.f;
        }
        __syncthreads();
        #pragma unroll
        for (int kk = 0; kk < 16; kk++) {
            float a4[4], b4[4];
            #pragma unroll
            for (int x = 0; x < 4; x++) a4[x] = As[kk][tm + x];
            #pragma unroll
            for (int y = 0; y < 4; y++) b4[y] = Bs[kk][tn + y];
            #pragma unroll
            for (int x = 0; x < 4; x++)
                #pragma unroll
                for (int y = 0; y < 4; y++) acc[x][y] += a4[x] * b4[y];
        }
        __syncthreads();
    }
    #pragma unroll
    for (int x = 0; x < 4; x++) {
        int rr = row0 + tm + x;
        if (rr >= M) continue;
        #pragma unroll
        for (int y = 0; y < 4; y++) {
            int cc = col0 + tn + y;
            if (cc >= N) continue;
            float v = acc[x][y];
            if (EPI == 1) v = tanhf(v + bias[cc]);
            C[(long)rr * N + cc] = v;
        }
    }
}

__global__ void sgemm_nt(const float* __restrict__ A, const float* __restrict__ B,
                         float* __restrict__ C, int M, int N, int K,
                         long sA, long sB, long sC)
{
    A += (long)blockIdx.z * sA;  B += (long)blockIdx.z * sB;  C += (long)blockIdx.z * sC;
    __shared__ float As[16][64];
    __shared__ float Bs[16][64];
    const int tid = threadIdx.x;
    const int row0 = blockIdx.y * 64, col0 = blockIdx.x * 64;
    const int tm = (tid >> 4) * 4, tn = (tid & 15) * 4;
    float acc[4][4] = {};
    for (int k0 = 0; k0 < K; k0 += 16) {
        #pragma unroll
        for (int i = 0; i < 4; i++) {
            int idx = tid + i * 256;
            int m = idx >> 4, kk = idx & 15;
            int gr = row0 + m, gc = k0 + kk;
            As[kk][m] = (gr < M && gc < K) ? A[(long)gr * K + gc] : 0.f;
        }
        #pragma unroll
        for (int i = 0; i < 4; i++) {
            int idx = tid + i * 256;
            int n = idx >> 4, kk = idx & 15;
            int gr = col0 + n, gc = k0 + kk;
            Bs[kk][n] = (gr < N && gc < K) ? B[(long)gr * K + gc] : 0.f;
        }
        __syncthreads();
        #pragma unroll
        for (int kk = 0; kk < 16; kk++) {
            float a4[4], b4[4];
            #pragma unroll
            for (int x = 0; x < 4; x++) a4[x] = As[kk][tm + x];
            #pragma unroll
            for (int y = 0; y < 4; y++) b4[y] = Bs[kk][tn + y];
            #pragma unroll
            for (int x = 0; x < 4; x++)
                #pragma unroll
                for (int y = 0; y < 4; y++) acc[x][y] += a4[x] * b4[y];
        }
        __syncthreads();
    }
    #pragma unroll
    for (int x = 0; x < 4; x++) {
        int rr = row0 + tm + x;
        if (rr >= M) continue;
        #pragma unroll
        for (int y = 0; y < 4; y++) {
            int cc = col0 + tn + y;
            if (cc >= N) continue;
            C[(long)rr * N + cc] = acc[x][y];
        }
    }
}

// ---------------- psi ----------------
__global__ void psi_kernel(const float* __restrict__ ent)
{
    int m = blockIdx.x;
    __shared__ float gs[D_];
    for (int d = threadIdx.x; d < D_; d += blockDim.x) gs[d] = d_g[m * D_ + d];
    __syncthreads();
    int w = threadIdx.x >> 5, lane = threadIdx.x & 31;
    for (int c = w; c < C_; c += (blockDim.x >> 5)) {
        const float* e = ent + ((long)m * C_ + c) * D_;
        float s = 0.f;
        for (int d = lane; d < D_; d += 32) s += e[d] * gs[d];
        #pragma unroll
        for (int o = 16; o; o >>= 1) s += __shfl_down_sync(0xffffffffu, s, o);
        if (lane == 0) d_psi[m * C_ + c] = s;
    }
}

// ---------------- a softmax ----------------
__global__ void a_kernel()
{
    int ij = blockIdx.x * blockDim.x + threadIdx.x;
    if (ij >= MM) return;
    const float scale = 0.05773502691896258f;
    float s0 = d_s[0 * MM + ij] * scale;
    float s1 = d_s[1 * MM + ij] * scale;
    float s2 = d_s[2 * MM + ij] * scale;
    float mx = fmaxf(s0, fmaxf(s1, s2));
    float e0 = expf(s0 - mx), e1 = expf(s1 - mx), e2 = expf(s2 - mx);
    float inv = 1.f / (e0 + e1 + e2);
    d_a[ij * 3 + 0] = e0 * inv;
    d_a[ij * 3 + 1] = e1 * inv;
    d_a[ij * 3 + 2] = e2 * inv;
}

// ---------------- LBP ----------------
__global__ void zero_kernel()
{
    int idx = blockIdx.x * blockDim.x + threadIdx.x;
    if (idx < M_ * M_ * C_) d_mbarA[idx] = 0.f;
}

__global__ void t_kernel(const float* __restrict__ mbar)
{
    int i = blockIdx.x;
    __shared__ float part[8][32];
    int t = threadIdx.x;
    int jg = t >> 5, p = t & 31;
    float s = 0.f;
    if (p < C_) {
        for (int j = jg; j < M_; j += 8) s += mbar[(j * M_ + i) * C_ + p];
    }
    part[jg][p] = s;
    __syncthreads();
    if (t < C_) {
        float tot = 0.f;
        #pragma unroll
        for (int g = 0; g < 8; g++) tot += part[g][t];
        d_t[i * C_ + t] = d_psi[i * C_ + t] + tot;
    }
}

__global__ void lbp_update(const float* __restrict__ mbar, float* __restrict__ mbarN)
{
    const int w = threadIdx.x >> 5;
    const int lane = threadIdx.x & 31;
    const int ij = blockIdx.x * 8 + w;
    const int i = ij / M_, j = ij % M_;
    __shared__ float tt[8][32];

    if (lane < C_)
        tt[w][lane] = d_t[i * C_ + lane] - mbar[(j * M_ + i) * C_ + lane];
    __syncwarp();

    const float* ph = d_phi + (size_t)(i * C_) * MC + j * C_;
    float mv = -1e30f;
    if (lane < C_) {
        #pragma unroll 6
        for (int p = 0; p < C_; p++)
            mv = fmaxf(mv, tt[w][p] + ph[(size_t)p * MC + lane]);
        mv = fmaxf(mv, 0.f);
    }
    float mx = (lane < C_) ? mv : -1e30f;
    #pragma unroll
    for (int o = 16; o; o >>= 1) mx = fmaxf(mx, __shfl_xor_sync(0xffffffffu, mx, o));
    float e = (lane < C_) ? __expf(mv - mx) : 0.f;
    float sum = e;
    #pragma unroll
    for (int o = 16; o; o >>= 1) sum += __shfl_xor_sync(0xffffffffu, sum, o);
    if (lane < C_) {
        float sm = e / sum;
        float old = mbar[ij * C_ + lane];
        mbarN[ij * C_ + lane] = __logf(0.5f * __expf(old) + 0.5f * sm);
    }
}

__global__ void final_kernel(float* __restrict__ out, const float* __restrict__ mbar)
{
    int i = blockIdx.x;
    int lane = threadIdx.x;
    float u = -1e30f;
    if (lane < C_) {
        float s = 0.f;
        for (int j = 0; j < M_; j++) s += mbar[(j * M_ + i) * C_ + lane];
        s -= mbar[(i * M_ + i) * C_ + lane];
        u = d_psi[i * C_ + lane] + s;
    }
    float mx = u;
    #pragma unroll
    for (int o = 16; o; o >>= 1) mx = fmaxf(mx, __shfl_xor_sync(0xffffffffu, mx, o));
    float e = (lane < C_) ? expf(u - mx) : 0.f;
    float sum = e;
    #pragma unroll
    for (int o = 16; o; o >>= 1) sum += __shfl_xor_sync(0xffffffffu, sum, o);
    if (lane < C_) out[i * C_ + lane] = e / sum;
}

// ---------------- host ----------------
extern "C" void kernel_launch(void* const* d_in, const int* in_sizes, int n_in,
                              void* d_out, int out_size)
{
    const float* ent    = (const float*)d_in[0];
    const float* fmc_in = (const float*)d_in[1];
    const float* W_fmc  = (const float*)d_in[2];
    const float* b_fmc  = (const float*)d_in[3];
    const float* Bmat   = (const float*)d_in[4];
    const float* Rmat   = (const float*)d_in[5];
    const float* Dmat   = (const float*)d_in[6];
    float* out = (float*)d_out;

    float *pf, *pg, *pfD, *ps, *pmA, *pmB;
    cudaGetSymbolAddress((void**)&pf,  d_f);
    cudaGetSymbolAddress((void**)&pg,  d_g);
    cudaGetSymbolAddress((void**)&pfD, d_fD);
    cudaGetSymbolAddress((void**)&ps,  d_s);
    cudaGetSymbolAddress((void**)&pmA, d_mbarA);
    cudaGetSymbolAddress((void**)&pmB, d_mbarB);

    cudaFuncSetAttribute(er_mma,  cudaFuncAttributeMaxDynamicSharedMemorySize, 2 * ER_BUF * 4);
    cudaFuncSetAttribute(phi_mma, cudaFuncAttributeMaxDynamicSharedMemorySize, 2 * PHI_BUF * 4);

    // packs (tf32-rounded, padded operands)
    pack_A <<<(RPAD * KPAD + 255) / 256, 256>>>(ent);
    pack_Rt<<<(K_ * NPAD * KPAD + 255) / 256, 256>>>(Rmat);

    // f = tanh(fmc_in @ W_fmc + b)
    sgemm_nn<1><<<dim3(5, 2, 1), 256>>>(fmc_in, W_fmc, pf, 100, 300, 900, 0, 0, 0, b_fmc);
    // g = f @ B^T
    sgemm_nt<<<dim3(5, 2, 1), 256>>>(pf, Bmat, pg, 100, 300, 300, 0, 0, 0);
    psi_kernel<<<100, 256>>>(ent);
    // fD_k = f @ D_k ; s_k = fD_k @ f^T
    sgemm_nn<0><<<dim3(5, 2, 3), 256>>>(pf, Dmat, pfD, 100, 300, 300, 0, 90000, 30000, nullptr);
    sgemm_nt<<<dim3(2, 2, 3), 256>>>(pfD, pf, ps, 100, 100, 300, 30000, 0, 10000);
    a_kernel<<<40, 256>>>();

    // ER_k = ent @ R_k (tf32 mma.sync)
    er_mma<<<dim3(5, 24, 3), 256, 2 * ER_BUF * 4>>>();
    // phi: 3 fused tf32 GEMMs + a-weighted epilogue
    phi_mma<<<dim3(47, 24), 256, 2 * PHI_BUF * 4>>>();

    // LBP: 10 damped iterations (ping-pong A<->B)
    zero_kernel<<<(M_ * M_ * C_ + 255) / 256, 256>>>();
    for (int it = 0; it < 10; it++) {
        const float* src = (it & 1) ? pmB : pmA;
        float*       dst = (it & 1) ? pmA : pmB;
        t_kernel<<<100, 256>>>(src);
        lbp_update<<<1250, 256>>>(src, dst);
    }
    final_kernel<<<100, 32>>>(out, pmA);
}

// round 5
// speedup vs baseline: 3.5769x; 1.4653x over previous
#include <cuda_runtime.h>
#include <cstdint>
#include <math.h>

#define M_    100
#define C_    30
#define D_    300
#define K_    3
#define MC    3000
#define MM    10000
#define KPAD  320            // padded K dim (20 chunks of 16)
#define RPAD  3072           // padded MC rows
#define NPAD  384            // padded rows for R^T
#define NCH   20             // K chunks of 16

// ---------------- scratch ----------------
static __device__ float d_f   [M_*D_];
static __device__ float d_g   [M_*D_];
static __device__ float d_psi [M_*C_];
static __device__ float d_fD  [K_*M_*D_];
static __device__ float d_s   [K_*M_*M_];
static __device__ float d_a   [M_*M_*K_];
static __device__ float d_Apad[RPAD*KPAD];
static __device__ float d_Bpad[K_*RPAD*KPAD];
static __device__ float d_Rt  [K_*NPAD*KPAD];
static __device__ float d_phi [MC*MC];            // 36 MB, [ip][jq]
static __device__ float d_mbarA[M_*M_*C_];
static __device__ float d_mbarB[M_*M_*C_];
static __device__ float d_S   [3][M_*C_];         // rotating stot buffers

// ---------------- helpers ----------------
__device__ __forceinline__ uint32_t smem_u32(const void* p) {
    uint32_t a;
    asm("{ .reg .u64 t; cvta.to.shared.u64 t, %1; cvt.u32.u64 %0, t; }" : "=r"(a) : "l"(p));
    return a;
}
__device__ __forceinline__ float to_tf32(float x) {
    float r; asm("cvt.rna.tf32.f32 %0, %1;" : "=f"(r) : "f"(x)); return r;
}
__device__ __forceinline__ void cpasync16(uint32_t dst, const void* src) {
    asm volatile("{\n\t.reg .u64 g;\n\tcvta.to.global.u64 g, %1;\n\t"
                 "cp.async.cg.shared.global [%0], [g], 16;\n\t}"
                 :: "r"(dst), "l"(src));
}
#define CP_COMMIT() asm volatile("cp.async.commit_group;" ::: "memory")
#define CP_WAIT(n)  asm volatile("cp.async.wait_group %0;" :: "n"(n) : "memory")

__device__ __forceinline__ void mma_tf32(float* c, const uint32_t* a, const uint32_t* b) {
    asm volatile("mma.sync.aligned.m16n8k8.row.col.f32.tf32.tf32.f32 "
        "{%0,%1,%2,%3}, {%4,%5,%6,%7}, {%8,%9}, {%0,%1,%2,%3};"
        : "+f"(c[0]), "+f"(c[1]), "+f"(c[2]), "+f"(c[3])
        : "r"(a[0]), "r"(a[1]), "r"(a[2]), "r"(a[3]), "r"(b[0]), "r"(b[1]));
}

// ---------------- zero_all: clear every accumulated buffer ------------------
__global__ void zero_all() {
    int idx = blockIdx.x * blockDim.x + threadIdx.x;
    int stride = gridDim.x * blockDim.x;
    for (int i = idx; i < M_*D_; i += stride) { d_f[i] = 0.f; d_g[i] = 0.f; }
    for (int i = idx; i < K_*M_*D_; i += stride) d_fD[i] = 0.f;
    for (int i = idx; i < K_*MM; i += stride) d_s[i] = 0.f;
    for (int i = idx; i < M_*M_*C_; i += stride) d_mbarA[i] = 0.f;
    for (int i = idx; i < M_*C_; i += stride) { d_S[0][i] = 0.f; d_S[1][i] = 0.f; }
}

// ---------------- pack kernels ----------------
__global__ void pack_A(const float* __restrict__ ent) {
    int idx = blockIdx.x * blockDim.x + threadIdx.x;
    if (idx >= RPAD * KPAD) return;
    int r = idx / KPAD, d = idx - r * KPAD;
    d_Apad[idx] = (r < MC && d < D_) ? to_tf32(ent[r * D_ + d]) : 0.f;
}
__global__ void pack_Rt(const float* __restrict__ R) {
    int idx = blockIdx.x * blockDim.x + threadIdx.x;
    if (idx >= K_ * NPAD * KPAD) return;
    int k = idx / (NPAD * KPAD);
    int rem = idx - k * (NPAD * KPAD);
    int n = rem / KPAD, d = rem - n * KPAD;
    d_Rt[idx] = (n < D_ && d < D_) ? to_tf32(R[k * D_ * D_ + d * D_ + n]) : 0.f;
}

// ================= ER via mma.sync tf32 (unchanged from R4) ===========
#define ER_BUF 3840
__global__ void __launch_bounds__(256) er_mma() {
    extern __shared__ uint32_t sm[];
    const int tid = threadIdx.x, lane = tid & 31, wid = tid >> 5;
    const int warpM = wid & 3, warpN = wid >> 2;
    const int row0 = blockIdx.y * 128;
    const int n0   = blockIdx.x * 64;
    const uint32_t smb = smem_u32(sm);
    const float4* Ag = (const float4*)(d_Apad + (size_t)row0 * KPAD);
    const float4* Bg = (const float4*)(d_Rt + (size_t)blockIdx.z * NPAD * KPAD
                                       + (size_t)n0 * KPAD);
    float acc[2][4][4] = {};

    auto prefetch = [&](int ch, int buf) {
        int c4o = ch * 4;
        uint32_t base = smb + buf * ER_BUF * 4;
        #pragma unroll
        for (int it = 0; it < 2; it++) {
            int idx = tid + it * 256;
            int m = idx >> 2, q = idx & 3;
            cpasync16(base + (m * 20 + q * 4) * 4, Ag + m * 80 + c4o + q);
        }
        {
            int n = tid >> 2, q = tid & 3;
            cpasync16(base + (2560 + n * 20 + q * 4) * 4, Bg + n * 80 + c4o + q);
        }
    };

    prefetch(0, 0);
    CP_COMMIT();
    for (int ch = 0; ch < NCH; ch++) {
        if (ch + 1 < NCH) { prefetch(ch + 1, (ch + 1) & 1); CP_COMMIT(); CP_WAIT(1); }
        else CP_WAIT(0);
        __syncthreads();
        const uint32_t* As = sm + (ch & 1) * ER_BUF;
        const uint32_t* Bs = As + 2560;
        #pragma unroll
        for (int ks = 0; ks < 2; ks++) {
            uint32_t af[2][4];
            #pragma unroll
            for (int mf = 0; mf < 2; mf++) {
                int r = warpM * 32 + mf * 16 + (lane >> 2);
                int c = ks * 8 + (lane & 3);
                af[mf][0] = As[r * 20 + c];
                af[mf][1] = As[(r + 8) * 20 + c];
                af[mf][2] = As[r * 20 + c + 4];
                af[mf][3] = As[(r + 8) * 20 + c + 4];
            }
            uint32_t bf[4][2];
            #pragma unroll
            for (int nf = 0; nf < 4; nf++) {
                int n = warpN * 32 + nf * 8 + (lane >> 2);
                int kk = ks * 8 + (lane & 3);
                bf[nf][0] = Bs[n * 20 + kk];
                bf[nf][1] = Bs[n * 20 + kk + 4];
            }
            #pragma unroll
            for (int mf = 0; mf < 2; mf++)
                #pragma unroll
                for (int nf = 0; nf < 4; nf++)
                    mma_tf32(acc[mf][nf], af[mf], bf[nf]);
        }
        __syncthreads();
    }

    float* Bout = d_Bpad + (size_t)blockIdx.z * RPAD * KPAD;
    #pragma unroll
    for (int mf = 0; mf < 2; mf++) {
        int r = row0 + warpM * 32 + mf * 16 + (lane >> 2);
        #pragma unroll
        for (int nf = 0; nf < 4; nf++) {
            int c = n0 + warpN * 32 + nf * 8 + (lane & 3) * 2;
            float2 v0 = make_float2(to_tf32(acc[mf][nf][0]), to_tf32(acc[mf][nf][1]));
            float2 v1 = make_float2(to_tf32(acc[mf][nf][2]), to_tf32(acc[mf][nf][3]));
            *(float2*)(Bout + (size_t)r * KPAD + c)       = v0;
            *(float2*)(Bout + (size_t)(r + 8) * KPAD + c) = v1;
        }
    }
}

// ================= phi via mma.sync tf32, 3 fused kinds (unchanged) ===
#define PHI_BUF 6400
__global__ void __launch_bounds__(256) phi_mma() {
    extern __shared__ uint32_t sm[];
    const int tid = threadIdx.x, lane = tid & 31, wid = tid >> 5;
    const int warpM = wid & 3, warpN = wid >> 2;
    const int row0 = blockIdx.y * 128;
    const int col0 = blockIdx.x * 64;
    const uint32_t smb = smem_u32(sm);
    const float4* Ag = (const float4*)(d_Apad + (size_t)row0 * KPAD);
    float acc[3][2][4][4] = {};

    auto prefetch = [&](int ch, int buf) {
        int c4o = ch * 4;
        uint32_t base = smb + buf * PHI_BUF * 4;
        #pragma unroll
        for (int it = 0; it < 2; it++) {
            int idx = tid + it * 256;
            int m = idx >> 2, q = idx & 3;
            cpasync16(base + (m * 20 + q * 4) * 4, Ag + m * 80 + c4o + q);
        }
        #pragma unroll
        for (int it = 0; it < 3; it++) {
            int idx = tid + it * 256;
            int kb = idx >> 8, rem = idx & 255;
            int n = rem >> 2, q = rem & 3;
            const float4* Bg = (const float4*)(d_Bpad + (size_t)kb * RPAD * KPAD
                                               + (size_t)col0 * KPAD);
            cpasync16(base + (2560 + kb * 1280 + n * 20 + q * 4) * 4,
                      Bg + n * 80 + c4o + q);
        }
    };

    prefetch(0, 0);
    CP_COMMIT();
    for (int ch = 0; ch < NCH; ch++) {
        if (ch + 1 < NCH) { prefetch(ch + 1, (ch + 1) & 1); CP_COMMIT(); CP_WAIT(1); }
        else CP_WAIT(0);
        __syncthreads();
        const uint32_t* As = sm + (ch & 1) * PHI_BUF;
        #pragma unroll
        for (int ks = 0; ks < 2; ks++) {
            uint32_t af[2][4];
            #pragma unroll
            for (int mf = 0; mf < 2; mf++) {
                int r = warpM * 32 + mf * 16 + (lane >> 2);
                int c = ks * 8 + (lane & 3);
                af[mf][0] = As[r * 20 + c];
                af[mf][1] = As[(r + 8) * 20 + c];
                af[mf][2] = As[r * 20 + c + 4];
                af[mf][3] = As[(r + 8) * 20 + c + 4];
            }
            #pragma unroll
            for (int kb = 0; kb < 3; kb++) {
                const uint32_t* Bs = As + 2560 + kb * 1280;
                uint32_t bf[4][2];
                #pragma unroll
                for (int nf = 0; nf < 4; nf++) {
                    int n = warpN * 32 + nf * 8 + (lane >> 2);
                    int kk = ks * 8 + (lane & 3);
                    bf[nf][0] = Bs[n * 20 + kk];
                    bf[nf][1] = Bs[n * 20 + kk + 4];
                }
                #pragma unroll
                for (int mf = 0; mf < 2; mf++)
                    #pragma unroll
                    for (int nf = 0; nf < 4; nf++)
                        mma_tf32(acc[kb][mf][nf], af[mf], bf[nf]);
            }
        }
        __syncthreads();
    }

    #pragma unroll
    for (int mf = 0; mf < 2; mf++) {
        #pragma unroll
        for (int half = 0; half < 2; half++) {
            int r = row0 + warpM * 32 + mf * 16 + (lane >> 2) + half * 8;
            if (r >= MC) continue;
            int i = r / C_;
            #pragma unroll
            for (int nf = 0; nf < 4; nf++) {
                int c = col0 + warpN * 32 + nf * 8 + (lane & 3) * 2;
                if (c >= MC) continue;
                int j = c / C_;
                const float* aw = d_a + (i * M_ + j) * 3;
                float w0 = aw[0], w1 = aw[1], w2 = aw[2];
                int e0 = half * 2;
                float v0 = acc[0][mf][nf][e0]     * w0 + acc[1][mf][nf][e0]     * w1
                         + acc[2][mf][nf][e0]     * w2;
                float v1 = acc[0][mf][nf][e0 + 1] * w0 + acc[1][mf][nf][e0 + 1] * w1
                         + acc[2][mf][nf][e0 + 1] * w2;
                *(float2*)(d_phi + (size_t)r * MC + c) = make_float2(v0, v1);
            }
        }
    }
}

// ---------------- split-K small GEMMs (fp32, atomicAdd epilogue) ------------
// NN: C[m,n] += sum_{k in chunk} A[m,k]*B[k,n]
__global__ void sgemm_nn_sk(const float* __restrict__ A, const float* __restrict__ B,
                            float* __restrict__ C, int M, int N, int K,
                            int KC, int KS, long sA, long sB, long sC)
{
    int batch = blockIdx.z / KS, kz = blockIdx.z % KS;
    A += (long)batch * sA;  B += (long)batch * sB;  C += (long)batch * sC;
    __shared__ float As[16][64];
    __shared__ float Bs[16][64];
    const int tid = threadIdx.x;
    const int row0 = blockIdx.y * 64, col0 = blockIdx.x * 64;
    const int tm = (tid >> 4) * 4, tn = (tid & 15) * 4;
    float acc[4][4] = {};
    int kend = min(K, (kz + 1) * KC);
    for (int k0 = kz * KC; k0 < kend; k0 += 16) {
        #pragma unroll
        for (int i = 0; i < 4; i++) {
            int idx = tid + i * 256;
            int m = idx >> 4, kk = idx & 15;
            int gr = row0 + m, gc = k0 + kk;
            As[kk][m] = (gr < M && gc < K) ? A[(long)gr * K + gc] : 0.f;
        }
        #pragma unroll
        for (int i = 0; i < 4; i++) {
            int idx = tid + i * 256;
            int kk = idx >> 6, n = idx & 63;
            int gr = k0 + kk, gc = col0 + n;
            Bs[kk][n] = (gr < K && gc < N) ? B[(long)gr * N + gc] : 0.f;
        }
        __syncthreads();
        #pragma unroll
        for (int kk = 0; kk < 16; kk++) {
            float a4[4], b4[4];
            #pragma unroll
            for (int x = 0; x < 4; x++) a4[x] = As[kk][tm + x];
            #pragma unroll
            for (int y = 0; y < 4; y++) b4[y] = Bs[kk][tn + y];
            #pragma unroll
            for (int x = 0; x < 4; x++)
                #pragma unroll
                for (int y = 0; y < 4; y++) acc[x][y] += a4[x] * b4[y];
        }
        __syncthreads();
    }
    #pragma unroll
    for (int x = 0; x < 4; x++) {
        int rr = row0 + tm + x;
        if (rr >= M) continue;
        #pragma unroll
        for (int y = 0; y < 4; y++) {
            int cc = col0 + tn + y;
            if (cc >= N) continue;
            atomicAdd(&C[(long)rr * N + cc], acc[x][y]);
        }
    }
}

// NT: C[m,n] += sum_{k in chunk} A[m,k]*B[n,k]
__global__ void sgemm_nt_sk(const float* __restrict__ A, const float* __restrict__ B,
                            float* __restrict__ C, int M, int N, int K,
                            int KC, int KS, long sA, long sB, long sC)
{
    int batch = blockIdx.z / KS, kz = blockIdx.z % KS;
    A += (long)batch * sA;  B += (long)batch * sB;  C += (long)batch * sC;
    __shared__ float As[16][64];
    __shared__ float Bs[16][64];
    const int tid = threadIdx.x;
    const int row0 = blockIdx.y * 64, col0 = blockIdx.x * 64;
    const int tm = (tid >> 4) * 4, tn = (tid & 15) * 4;
    float acc[4][4] = {};
    int kend = min(K, (kz + 1) * KC);
    for (int k0 = kz * KC; k0 < kend; k0 += 16) {
        #pragma unroll
        for (int i = 0; i < 4; i++) {
            int idx = tid + i * 256;
            int m = idx >> 4, kk = idx & 15;
            int gr = row0 + m, gc = k0 + kk;
            As[kk][m] = (gr < M && gc < K) ? A[(long)gr * K + gc] : 0.f;
        }
        #pragma unroll
        for (int i = 0; i < 4; i++) {
            int idx = tid + i * 256;
            int n = idx >> 4, kk = idx & 15;
            int gr = col0 + n, gc = k0 + kk;
            Bs[kk][n] = (gr < N && gc < K) ? B[(long)gr * K + gc] : 0.f;
        }
        __syncthreads();
        #pragma unroll
        for (int kk = 0; kk < 16; kk++) {
            float a4[4], b4[4];
            #pragma unroll
            for (int x = 0; x < 4; x++) a4[x] = As[kk][tm + x];
            #pragma unroll
            for (int y = 0; y < 4; y++) b4[y] = Bs[kk][tn + y];
            #pragma unroll
            for (int x = 0; x < 4; x++)
                #pragma unroll
                for (int y = 0; y < 4; y++) acc[x][y] += a4[x] * b4[y];
        }
        __syncthreads();
    }
    #pragma unroll
    for (int x = 0; x < 4; x++) {
        int rr = row0 + tm + x;
        if (rr >= M) continue;
        #pragma unroll
        for (int y = 0; y < 4; y++) {
            int cc = col0 + tn + y;
            if (cc >= N) continue;
            atomicAdd(&C[(long)rr * N + cc], acc[x][y]);
        }
    }
}

// f epilogue: f = tanh(facc + bias)
__global__ void ftanh(const float* __restrict__ bias) {
    int idx = blockIdx.x * blockDim.x + threadIdx.x;
    if (idx >= M_ * D_) return;
    d_f[idx] = tanhf(d_f[idx] + bias[idx % D_]);
}

// ---------------- psi ----------------
__global__ void psi_kernel(const float* __restrict__ ent)
{
    int m = blockIdx.x;
    __shared__ float gs[D_];
    for (int d = threadIdx.x; d < D_; d += blockDim.x) gs[d] = d_g[m * D_ + d];
    __syncthreads();
    int w = threadIdx.x >> 5, lane = threadIdx.x & 31;
    for (int c = w; c < C_; c += (blockDim.x >> 5)) {
        const float* e = ent + ((long)m * C_ + c) * D_;
        float s = 0.f;
        for (int d = lane; d < D_; d += 32) s += e[d] * gs[d];
        #pragma unroll
        for (int o = 16; o; o >>= 1) s += __shfl_down_sync(0xffffffffu, s, o);
        if (lane == 0) d_psi[m * C_ + c] = s;
    }
}

// ---------------- a softmax ----------------
__global__ void a_kernel()
{
    int ij = blockIdx.x * blockDim.x + threadIdx.x;
    if (ij >= MM) return;
    const float scale = 0.05773502691896258f;
    float s0 = d_s[0 * MM + ij] * scale;
    float s1 = d_s[1 * MM + ij] * scale;
    float s2 = d_s[2 * MM + ij] * scale;
    float mx = fmaxf(s0, fmaxf(s1, s2));
    float e0 = expf(s0 - mx), e1 = expf(s1 - mx), e2 = expf(s2 - mx);
    float inv = 1.f / (e0 + e1 + e2);
    d_a[ij * 3 + 0] = e0 * inv;
    d_a[ij * 3 + 1] = e1 * inv;
    d_a[ij * 3 + 2] = e2 * inv;
}

// ---------------- fused LBP iteration ----------------
// grid 1000 blocks x 320 thr. Block b: receiver j = b%100, senders i = (b/100)*10 + w.
// Reads stot_src (= psi-less column sums of mbar_src), writes mbar_dst and
// accumulates new-message column sums into stot_dst. Blocks 0..11 zero stot_zero
// (the buffer that becomes stot_dst NEXT iteration; untouched by this launch).
__global__ void __launch_bounds__(320) lbp_fused(
    const float* __restrict__ mb_src, float* __restrict__ mb_dst,
    const float* __restrict__ stot_src, float* __restrict__ stot_dst,
    float* __restrict__ stot_zero)
{
    const int tid = threadIdx.x;
    const int w = tid >> 5, lane = tid & 31;
    const int b = blockIdx.x;
    const int j = b % M_;
    const int i = (b / M_) * 10 + w;
    __shared__ float tt[10][32];
    __shared__ float sred[10][32];

    if (b < 12) {
        int z = b * 320 + tid;
        if (z < M_ * C_) stot_zero[z] = 0.f;
    }

    if (lane < C_)
        tt[w][lane] = d_psi[i * C_ + lane] + stot_src[i * C_ + lane]
                    - mb_src[(j * M_ + i) * C_ + lane];
    __syncwarp();

    const float* ph = d_phi + (size_t)(i * C_) * MC + j * C_;
    float mv = -1e30f;
    if (lane < C_) {
        #pragma unroll 6
        for (int p = 0; p < C_; p++)
            mv = fmaxf(mv, tt[w][p] + ph[(size_t)p * MC + lane]);
        mv = fmaxf(mv, 0.f);
    }
    float mx = (lane < C_) ? mv : -1e30f;
    #pragma unroll
    for (int o = 16; o; o >>= 1) mx = fmaxf(mx, __shfl_xor_sync(0xffffffffu, mx, o));
    float e = (lane < C_) ? __expf(mv - mx) : 0.f;
    float sum = e;
    #pragma unroll
    for (int o = 16; o; o >>= 1) sum += __shfl_xor_sync(0xffffffffu, sum, o);

    float newm = 0.f;
    if (lane < C_) {
        float sm = e / sum;
        float old = mb_src[(i * M_ + j) * C_ + lane];
        newm = __logf(0.5f * __expf(old) + 0.5f * sm);
        mb_dst[(i * M_ + j) * C_ + lane] = newm;
    }
    sred[w][lane] = newm;
    __syncthreads();

    // partial column sums for receiver j -> stot_dst[j, q]
    if (tid < C_) {
        float s = 0.f;
        #pragma unroll
        for (int w2 = 0; w2 < 10; w2++) s += sred[w2][tid];
        atomicAdd(&stot_dst[j * C_ + tid], s);
    }
}

// out[i,:] = softmax_q( psi[i,q] + stot[i,q] - mbar[i,i,q] )
__global__ void final_kernel(float* __restrict__ out, const float* __restrict__ mbar,
                             const float* __restrict__ stot)
{
    int i = blockIdx.x;
    int lane = threadIdx.x;
    float u = -1e30f;
    if (lane < C_)
        u = d_psi[i * C_ + lane] + stot[i * C_ + lane]
          - mbar[(i * M_ + i) * C_ + lane];
    float mx = u;
    #pragma unroll
    for (int o = 16; o; o >>= 1) mx = fmaxf(mx, __shfl_xor_sync(0xffffffffu, mx, o));
    float e = (lane < C_) ? expf(u - mx) : 0.f;
    float sum = e;
    #pragma unroll
    for (int o = 16; o; o >>= 1) sum += __shfl_xor_sync(0xffffffffu, sum, o);
    if (lane < C_) out[i * C_ + lane] = e / sum;
}

// ---------------- host ----------------
extern "C" void kernel_launch(void* const* d_in, const int* in_sizes, int n_in,
                              void* d_out, int out_size)
{
    const float* ent    = (const float*)d_in[0];
    const float* fmc_in = (const float*)d_in[1];
    const float* W_fmc  = (const float*)d_in[2];
    const float* b_fmc  = (const float*)d_in[3];
    const float* Bmat   = (const float*)d_in[4];
    const float* Rmat   = (const float*)d_in[5];
    const float* Dmat   = (const float*)d_in[6];
    float* out = (float*)d_out;

    float *pf, *pg, *pfD, *ps, *pmA, *pmB, *pS;
    cudaGetSymbolAddress((void**)&pf,  d_f);
    cudaGetSymbolAddress((void**)&pg,  d_g);
    cudaGetSymbolAddress((void**)&pfD, d_fD);
    cudaGetSymbolAddress((void**)&ps,  d_s);
    cudaGetSymbolAddress((void**)&pmA, d_mbarA);
    cudaGetSymbolAddress((void**)&pmB, d_mbarB);
    cudaGetSymbolAddress((void**)&pS,  d_S);
    float* S[3] = { pS, pS + M_*C_, pS + 2*M_*C_ };

    cudaFuncSetAttribute(er_mma,  cudaFuncAttributeMaxDynamicSharedMemorySize, 2 * ER_BUF * 4);
    cudaFuncSetAttribute(phi_mma, cudaFuncAttributeMaxDynamicSharedMemorySize, 2 * PHI_BUF * 4);

    // clear all accumulated buffers (f,g,fD,s, mbarA, S0, S1)
    zero_all<<<512, 256>>>();

    // tf32-packed operands for the MMA path
    pack_A <<<(RPAD * KPAD + 255) / 256, 256>>>(ent);
    pack_Rt<<<(K_ * NPAD * KPAD + 255) / 256, 256>>>(Rmat);

    // f = tanh(fmc_in @ W_fmc + b): split-K 5
    sgemm_nn_sk<<<dim3(5, 2, 5), 256>>>(fmc_in, W_fmc, pf, 100, 300, 900, 192, 5, 0, 0, 0);
    ftanh<<<(M_ * D_ + 255) / 256, 256>>>(b_fmc);
    // g = f @ B^T: split-K 3
    sgemm_nt_sk<<<dim3(5, 2, 3), 256>>>(pf, Bmat, pg, 100, 300, 300, 112, 3, 0, 0, 0);
    psi_kernel<<<100, 256>>>(ent);
    // fD_k = f @ D_k: batch 3 x split-K 3
    sgemm_nn_sk<<<dim3(5, 2, 9), 256>>>(pf, Dmat, pfD, 100, 300, 300, 112, 3, 0, 90000, 30000);
    // s_k = fD_k @ f^T: batch 3 x split-K 3
    sgemm_nt_sk<<<dim3(2, 2, 9), 256>>>(pfD, pf, ps, 100, 100, 300, 112, 3, 30000, 0, 10000);
    a_kernel<<<40, 256>>>();

    // tensor-core GEMMs
    er_mma<<<dim3(5, 24, 3), 256, 2 * ER_BUF * 4>>>();
    phi_mma<<<dim3(47, 24), 256, 2 * PHI_BUF * 4>>>();

    // fused LBP: 10 damped iterations; mbar ping-pong A<->B, stot rotates S0/S1/S2
    for (int it = 0; it < 10; it++) {
        const float* msrc = (it & 1) ? pmB : pmA;
        float*       mdst = (it & 1) ? pmA : pmB;
        lbp_fused<<<1000, 320>>>(msrc, mdst,
                                 S[it % 3], S[(it + 1) % 3], S[(it + 2) % 3]);
    }
    // final: mbar in A (it=9 wrote A), stot in S[(9+1)%3] = S[1]
    final_kernel<<<100, 32>>>(out, pmA, S[1]);
}

// round 6
// speedup vs baseline: 3.8598x; 1.0791x over previous
#include <cuda_runtime.h>
#include <cstdint>
#include <math.h>

#define M_    100
#define C_    30
#define D_    300
#define K_    3
#define MC    3000
#define MM    10000
#define KPAD  320            // padded K dim (20 chunks of 16)
#define RPAD  3072           // padded MC rows
#define NPAD  384            // padded rows for R^T
#define NCH   20             // K chunks of 16

// ---------------- scratch ----------------
static __device__ float d_f   [M_*D_];
static __device__ float d_g   [M_*D_];
static __device__ float d_psi [M_*C_];
static __device__ float d_fD  [K_*M_*D_];
static __device__ float d_s   [K_*M_*M_];
static __device__ float d_a   [M_*M_*K_];
static __device__ float d_Bt  [D_*D_];            // B^T (fp32 exact)
static __device__ float d_Apad[RPAD*KPAD];
static __device__ float d_Bpad[K_*RPAD*KPAD];
static __device__ float d_Rt  [K_*NPAD*KPAD];
static __device__ float d_phi [MC*MC];            // 36 MB, [ip][jq]
static __device__ float d_mbarA[M_*M_*C_];
static __device__ float d_mbarB[M_*M_*C_];
static __device__ float d_S   [3][M_*C_];         // rotating stot buffers

// ---------------- helpers ----------------
__device__ __forceinline__ uint32_t smem_u32(const void* p) {
    uint32_t a;
    asm("{ .reg .u64 t; cvta.to.shared.u64 t, %1; cvt.u32.u64 %0, t; }" : "=r"(a) : "l"(p));
    return a;
}
__device__ __forceinline__ float to_tf32(float x) {
    float r; asm("cvt.rna.tf32.f32 %0, %1;" : "=f"(r) : "f"(x)); return r;
}
__device__ __forceinline__ void cpasync16(uint32_t dst, const void* src) {
    asm volatile("{\n\t.reg .u64 g;\n\tcvta.to.global.u64 g, %1;\n\t"
                 "cp.async.cg.shared.global [%0], [g], 16;\n\t}"
                 :: "r"(dst), "l"(src));
}
// cp.async with runtime src-size (0..16); bytes beyond src-size are zero-filled
__device__ __forceinline__ void cpasync16z(uint32_t dst, const void* src, int bytes) {
    asm volatile("{\n\t.reg .u64 g;\n\tcvta.to.global.u64 g, %1;\n\t"
                 "cp.async.cg.shared.global [%0], [g], 16, %2;\n\t}"
                 :: "r"(dst), "l"(src), "r"(bytes));
}
__device__ __forceinline__ void cpasync4z(uint32_t dst, const void* src, int bytes) {
    asm volatile("{\n\t.reg .u64 g;\n\tcvta.to.global.u64 g, %1;\n\t"
                 "cp.async.ca.shared.global [%0], [g], 4, %2;\n\t}"
                 :: "r"(dst), "l"(src), "r"(bytes));
}
#define CP_COMMIT() asm volatile("cp.async.commit_group;" ::: "memory")
#define CP_WAIT(n)  asm volatile("cp.async.wait_group %0;" :: "n"(n) : "memory")

__device__ __forceinline__ void mma_tf32(float* c, const uint32_t* a, const uint32_t* b) {
    asm volatile("mma.sync.aligned.m16n8k8.row.col.f32.tf32.tf32.f32 "
        "{%0,%1,%2,%3}, {%4,%5,%6,%7}, {%8,%9}, {%0,%1,%2,%3};"
        : "+f"(c[0]), "+f"(c[1]), "+f"(c[2]), "+f"(c[3])
        : "r"(a[0]), "r"(a[1]), "r"(a[2]), "r"(a[3]), "r"(b[0]), "r"(b[1]));
}

// ---------------- mega_pack: all zeroing + operand packing, one launch ------
__global__ void mega_pack(const float* __restrict__ ent, const float* __restrict__ R,
                          const float* __restrict__ Bm) {
    int idx = blockIdx.x * blockDim.x + threadIdx.x;
    int stride = gridDim.x * blockDim.x;
    // zero accumulated buffers
    for (int i = idx; i < M_*D_; i += stride) { d_f[i] = 0.f; d_g[i] = 0.f; }
    for (int i = idx; i < K_*M_*D_; i += stride) d_fD[i] = 0.f;
    for (int i = idx; i < K_*MM; i += stride) d_s[i] = 0.f;
    for (int i = idx; i < M_*M_*C_; i += stride) d_mbarA[i] = 0.f;
    for (int i = idx; i < M_*C_; i += stride) { d_S[0][i] = 0.f; d_S[1][i] = 0.f; }
    // B^T (exact fp32)
    for (int i = idx; i < D_*D_; i += stride) {
        int dd = i / D_, e = i - dd * D_;
        d_Bt[i] = Bm[e * D_ + dd];
    }
    // tf32-packed ent (padded)
    for (int i = idx; i < RPAD*KPAD; i += stride) {
        int r = i / KPAD, d = i - r * KPAD;
        d_Apad[i] = (r < MC && d < D_) ? to_tf32(ent[r * D_ + d]) : 0.f;
    }
    // tf32-packed R^T (padded)
    for (int i = idx; i < K_*NPAD*KPAD; i += stride) {
        int k = i / (NPAD * KPAD);
        int rem = i - k * (NPAD * KPAD);
        int n = rem / KPAD, d = rem - n * KPAD;
        d_Rt[i] = (n < D_ && d < D_) ? to_tf32(R[k * D_ * D_ + d * D_ + n]) : 0.f;
    }
}

// ================= ER via mma.sync tf32 (unchanged) ===================
#define ER_BUF 3840
__global__ void __launch_bounds__(256) er_mma() {
    extern __shared__ uint32_t sm[];
    const int tid = threadIdx.x, lane = tid & 31, wid = tid >> 5;
    const int warpM = wid & 3, warpN = wid >> 2;
    const int row0 = blockIdx.y * 128;
    const int n0   = blockIdx.x * 64;
    const uint32_t smb = smem_u32(sm);
    const float4* Ag = (const float4*)(d_Apad + (size_t)row0 * KPAD);
    const float4* Bg = (const float4*)(d_Rt + (size_t)blockIdx.z * NPAD * KPAD
                                       + (size_t)n0 * KPAD);
    float acc[2][4][4] = {};

    auto prefetch = [&](int ch, int buf) {
        int c4o = ch * 4;
        uint32_t base = smb + buf * ER_BUF * 4;
        #pragma unroll
        for (int it = 0; it < 2; it++) {
            int idx = tid + it * 256;
            int m = idx >> 2, q = idx & 3;
            cpasync16(base + (m * 20 + q * 4) * 4, Ag + m * 80 + c4o + q);
        }
        {
            int n = tid >> 2, q = tid & 3;
            cpasync16(base + (2560 + n * 20 + q * 4) * 4, Bg + n * 80 + c4o + q);
        }
    };

    prefetch(0, 0);
    CP_COMMIT();
    for (int ch = 0; ch < NCH; ch++) {
        if (ch + 1 < NCH) { prefetch(ch + 1, (ch + 1) & 1); CP_COMMIT(); CP_WAIT(1); }
        else CP_WAIT(0);
        __syncthreads();
        const uint32_t* As = sm + (ch & 1) * ER_BUF;
        const uint32_t* Bs = As + 2560;
        #pragma unroll
        for (int ks = 0; ks < 2; ks++) {
            uint32_t af[2][4];
            #pragma unroll
            for (int mf = 0; mf < 2; mf++) {
                int r = warpM * 32 + mf * 16 + (lane >> 2);
                int c = ks * 8 + (lane & 3);
                af[mf][0] = As[r * 20 + c];
                af[mf][1] = As[(r + 8) * 20 + c];
                af[mf][2] = As[r * 20 + c + 4];
                af[mf][3] = As[(r + 8) * 20 + c + 4];
            }
            uint32_t bf[4][2];
            #pragma unroll
            for (int nf = 0; nf < 4; nf++) {
                int n = warpN * 32 + nf * 8 + (lane >> 2);
                int kk = ks * 8 + (lane & 3);
                bf[nf][0] = Bs[n * 20 + kk];
                bf[nf][1] = Bs[n * 20 + kk + 4];
            }
            #pragma unroll
            for (int mf = 0; mf < 2; mf++)
                #pragma unroll
                for (int nf = 0; nf < 4; nf++)
                    mma_tf32(acc[mf][nf], af[mf], bf[nf]);
        }
        __syncthreads();
    }

    float* Bout = d_Bpad + (size_t)blockIdx.z * RPAD * KPAD;
    #pragma unroll
    for (int mf = 0; mf < 2; mf++) {
        int r = row0 + warpM * 32 + mf * 16 + (lane >> 2);
        #pragma unroll
        for (int nf = 0; nf < 4; nf++) {
            int c = n0 + warpN * 32 + nf * 8 + (lane & 3) * 2;
            float2 v0 = make_float2(to_tf32(acc[mf][nf][0]), to_tf32(acc[mf][nf][1]));
            float2 v1 = make_float2(to_tf32(acc[mf][nf][2]), to_tf32(acc[mf][nf][3]));
            *(float2*)(Bout + (size_t)r * KPAD + c)       = v0;
            *(float2*)(Bout + (size_t)(r + 8) * KPAD + c) = v1;
        }
    }
}

// ================= phi via mma.sync tf32, 3 fused kinds (unchanged) ===
#define PHI_BUF 6400
__global__ void __launch_bounds__(256) phi_mma() {
    extern __shared__ uint32_t sm[];
    const int tid = threadIdx.x, lane = tid & 31, wid = tid >> 5;
    const int warpM = wid & 3, warpN = wid >> 2;
    const int row0 = blockIdx.y * 128;
    const int col0 = blockIdx.x * 64;
    const uint32_t smb = smem_u32(sm);
    const float4* Ag = (const float4*)(d_Apad + (size_t)row0 * KPAD);
    float acc[3][2][4][4] = {};

    auto prefetch = [&](int ch, int buf) {
        int c4o = ch * 4;
        uint32_t base = smb + buf * PHI_BUF * 4;
        #pragma unroll
        for (int it = 0; it < 2; it++) {
            int idx = tid + it * 256;
            int m = idx >> 2, q = idx & 3;
            cpasync16(base + (m * 20 + q * 4) * 4, Ag + m * 80 + c4o + q);
        }
        #pragma unroll
        for (int it = 0; it < 3; it++) {
            int idx = tid + it * 256;
            int kb = idx >> 8, rem = idx & 255;
            int n = rem >> 2, q = rem & 3;
            const float4* Bg = (const float4*)(d_Bpad + (size_t)kb * RPAD * KPAD
                                               + (size_t)col0 * KPAD);
            cpasync16(base + (2560 + kb * 1280 + n * 20 + q * 4) * 4,
                      Bg + n * 80 + c4o + q);
        }
    };

    prefetch(0, 0);
    CP_COMMIT();
    for (int ch = 0; ch < NCH; ch++) {
        if (ch + 1 < NCH) { prefetch(ch + 1, (ch + 1) & 1); CP_COMMIT(); CP_WAIT(1); }
        else CP_WAIT(0);
        __syncthreads();
        const uint32_t* As = sm + (ch & 1) * PHI_BUF;
        #pragma unroll
        for (int ks = 0; ks < 2; ks++) {
            uint32_t af[2][4];
            #pragma unroll
            for (int mf = 0; mf < 2; mf++) {
                int r = warpM * 32 + mf * 16 + (lane >> 2);
                int c = ks * 8 + (lane & 3);
                af[mf][0] = As[r * 20 + c];
                af[mf][1] = As[(r + 8) * 20 + c];
                af[mf][2] = As[r * 20 + c + 4];
                af[mf][3] = As[(r + 8) * 20 + c + 4];
            }
            #pragma unroll
            for (int kb = 0; kb < 3; kb++) {
                const uint32_t* Bs = As + 2560 + kb * 1280;
                uint32_t bf[4][2];
                #pragma unroll
                for (int nf = 0; nf < 4; nf++) {
                    int n = warpN * 32 + nf * 8 + (lane >> 2);
                    int kk = ks * 8 + (lane & 3);
                    bf[nf][0] = Bs[n * 20 + kk];
                    bf[nf][1] = Bs[n * 20 + kk + 4];
                }
                #pragma unroll
                for (int mf = 0; mf < 2; mf++)
                    #pragma unroll
                    for (int nf = 0; nf < 4; nf++)
                        mma_tf32(acc[kb][mf][nf], af[mf], bf[nf]);
            }
        }
        __syncthreads();
    }

    #pragma unroll
    for (int mf = 0; mf < 2; mf++) {
        #pragma unroll
        for (int half = 0; half < 2; half++) {
            int r = row0 + warpM * 32 + mf * 16 + (lane >> 2) + half * 8;
            if (r >= MC) continue;
            int i = r / C_;
            #pragma unroll
            for (int nf = 0; nf < 4; nf++) {
                int c = col0 + warpN * 32 + nf * 8 + (lane & 3) * 2;
                if (c >= MC) continue;
                int j = c / C_;
                const float* aw = d_a + (i * M_ + j) * 3;
                float w0 = aw[0], w1 = aw[1], w2 = aw[2];
                int e0 = half * 2;
                float v0 = acc[0][mf][nf][e0]     * w0 + acc[1][mf][nf][e0]     * w1
                         + acc[2][mf][nf][e0]     * w2;
                float v1 = acc[0][mf][nf][e0 + 1] * w0 + acc[1][mf][nf][e0 + 1] * w1
                         + acc[2][mf][nf][e0 + 1] * w2;
                *(float2*)(d_phi + (size_t)r * MC + c) = make_float2(v0, v1);
            }
        }
    }
}

// ============ cp.async double-buffered split-K fp32 GEMMs ==================
// NN: C[m,n] += sum_k A[m,k]*B[k,n].  A shared across batches; batch 0 uses
// (B0, C0), batches 1.. use (B1 + (b-1)*sB, C1 + (b-1)*sC).
__global__ void __launch_bounds__(256) gemm_nn_ca(
    const float* __restrict__ A, const float* __restrict__ B0,
    const float* __restrict__ B1, float* __restrict__ C0, float* __restrict__ C1,
    int M, int N, int K, int KC, int KS, long sB, long sC)
{
    __shared__ float As[2][64][20];
    __shared__ float Bs[2][16][64];
    const int batch = blockIdx.z / KS, kz = blockIdx.z % KS;
    const float* Bp = (batch == 0) ? B0 : B1 + (long)(batch - 1) * sB;
    float*       Cp = (batch == 0) ? C0 : C1 + (long)(batch - 1) * sC;
    const int tid = threadIdx.x;
    const int row0 = blockIdx.y * 64, col0 = blockIdx.x * 64;
    const int tm = (tid >> 4) * 4, tn = (tid & 15) * 4;
    const int k0 = kz * KC, kend = min(K, k0 + KC);
    const int S = (kend - k0 + 15) >> 4;
    float acc[4][4] = {};

    auto prefetch = [&](int s, int buf) {
        int kb = k0 + s * 16;
        {   // A: 64 rows x 4 float4
            int m = tid >> 2, q = tid & 3;
            int gr = row0 + m, gc = kb + q * 4;
            int bytes = (gr < M && gc < kend) ? min(16, (kend - gc) * 4) : 0;
            cpasync16z(smem_u32(&As[buf][m][q * 4]), A + (long)gr * K + gc, bytes);
        }
        {   // B: 16 rows x 16 float4
            int kk = tid >> 4, q = tid & 15;
            int gr = kb + kk, gc = col0 + q * 4;
            int bytes = (gr < kend && gc < N) ? min(16, (N - gc) * 4) : 0;
            cpasync16z(smem_u32(&Bs[buf][kk][q * 4]), Bp + (long)gr * N + gc, bytes);
        }
    };

    prefetch(0, 0);
    CP_COMMIT();
    for (int s = 0; s < S; s++) {
        if (s + 1 < S) { prefetch(s + 1, (s + 1) & 1); CP_COMMIT(); CP_WAIT(1); }
        else CP_WAIT(0);
        __syncthreads();
        int buf = s & 1;
        #pragma unroll
        for (int kk = 0; kk < 16; kk++) {
            float a4[4], b4[4];
            #pragma unroll
            for (int x = 0; x < 4; x++) a4[x] = As[buf][tm + x][kk];
            #pragma unroll
            for (int y = 0; y < 4; y++) b4[y] = Bs[buf][kk][tn + y];
            #pragma unroll
            for (int x = 0; x < 4; x++)
                #pragma unroll
                for (int y = 0; y < 4; y++) acc[x][y] += a4[x] * b4[y];
        }
        __syncthreads();
    }
    #pragma unroll
    for (int x = 0; x < 4; x++) {
        int rr = row0 + tm + x;
        if (rr >= M) continue;
        #pragma unroll
        for (int y = 0; y < 4; y++) {
            int cc = col0 + tn + y;
            if (cc >= N) continue;
            atomicAdd(&Cp[(long)rr * N + cc], acc[x][y]);
        }
    }
}

// NT: C[m,n] += sum_k A[m,k]*B[n,k].  B shared; A/C batched.
__global__ void __launch_bounds__(256) gemm_nt_ca(
    const float* __restrict__ A, const float* __restrict__ B, float* __restrict__ C,
    int M, int N, int K, int KC, int KS, long sA, long sC)
{
    __shared__ float As[2][64][20];
    __shared__ float Bs[2][16][68];
    const int batch = blockIdx.z / KS, kz = blockIdx.z % KS;
    const float* Ap = A + (long)batch * sA;
    float*       Cp = C + (long)batch * sC;
    const int tid = threadIdx.x;
    const int row0 = blockIdx.y * 64, col0 = blockIdx.x * 64;
    const int tm = (tid >> 4) * 4, tn = (tid & 15) * 4;
    const int k0 = kz * KC, kend = min(K, k0 + KC);
    const int S = (kend - k0 + 15) >> 4;
    float acc[4][4] = {};

    auto prefetch = [&](int s, int buf) {
        int kb = k0 + s * 16;
        {   // A: 64 rows x 4 float4
            int m = tid >> 2, q = tid & 3;
            int gr = row0 + m, gc = kb + q * 4;
            int bytes = (gr < M && gc < kend) ? min(16, (kend - gc) * 4) : 0;
            cpasync16z(smem_u32(&As[buf][m][q * 4]), Ap + (long)gr * K + gc, bytes);
        }
        // B: 64 n-rows x 16 kk, 4B each, stored transposed Bs[kk][n]
        #pragma unroll
        for (int it = 0; it < 4; it++) {
            int idx = tid + it * 256;
            int n = idx >> 4, kk = idx & 15;
            int gr = col0 + n, gc = kb + kk;
            int bytes = (gr < N && gc < kend) ? 4 : 0;
            cpasync4z(smem_u32(&Bs[buf][kk][n]), B + (long)gr * K + gc, bytes);
        }
    };

    prefetch(0, 0);
    CP_COMMIT();
    for (int s = 0; s < S; s++) {
        if (s + 1 < S) { prefetch(s + 1, (s + 1) & 1); CP_COMMIT(); CP_WAIT(1); }
        else CP_WAIT(0);
        __syncthreads();
        int buf = s & 1;
        #pragma unroll
        for (int kk = 0; kk < 16; kk++) {
            float a4[4], b4[4];
            #pragma unroll
            for (int x = 0; x < 4; x++) a4[x] = As[buf][tm + x][kk];
            #pragma unroll
            for (int y = 0; y < 4; y++) b4[y] = Bs[buf][kk][tn + y];
            #pragma unroll
            for (int x = 0; x < 4; x++)
                #pragma unroll
                for (int y = 0; y < 4; y++) acc[x][y] += a4[x] * b4[y];
        }
        __syncthreads();
    }
    #pragma unroll
    for (int x = 0; x < 4; x++) {
        int rr = row0 + tm + x;
        if (rr >= M) continue;
        #pragma unroll
        for (int y = 0; y < 4; y++) {
            int cc = col0 + tn + y;
            if (cc >= N) continue;
            atomicAdd(&Cp[(long)rr * N + cc], acc[x][y]);
        }
    }
}

// f epilogue: f = tanh(facc + bias)
__global__ void ftanh(const float* __restrict__ bias) {
    int idx = blockIdx.x * blockDim.x + threadIdx.x;
    if (idx >= M_ * D_) return;
    d_f[idx] = tanhf(d_f[idx] + bias[idx % D_]);
}

// ---------------- psi ----------------
__global__ void psi_kernel(const float* __restrict__ ent)
{
    int m = blockIdx.x;
    __shared__ float gs[D_];
    for (int d = threadIdx.x; d < D_; d += blockDim.x) gs[d] = d_g[m * D_ + d];
    __syncthreads();
    int w = threadIdx.x >> 5, lane = threadIdx.x & 31;
    for (int c = w; c < C_; c += (blockDim.x >> 5)) {
        const float* e = ent + ((long)m * C_ + c) * D_;
        float s = 0.f;
        for (int d = lane; d < D_; d += 32) s += e[d] * gs[d];
        #pragma unroll
        for (int o = 16; o; o >>= 1) s += __shfl_down_sync(0xffffffffu, s, o);
        if (lane == 0) d_psi[m * C_ + c] = s;
    }
}

// ---------------- a softmax ----------------
__global__ void a_kernel()
{
    int ij = blockIdx.x * blockDim.x + threadIdx.x;
    if (ij >= MM) return;
    const float scale = 0.05773502691896258f;
    float s0 = d_s[0 * MM + ij] * scale;
    float s1 = d_s[1 * MM + ij] * scale;
    float s2 = d_s[2 * MM + ij] * scale;
    float mx = fmaxf(s0, fmaxf(s1, s2));
    float e0 = expf(s0 - mx), e1 = expf(s1 - mx), e2 = expf(s2 - mx);
    float inv = 1.f / (e0 + e1 + e2);
    d_a[ij * 3 + 0] = e0 * inv;
    d_a[ij * 3 + 1] = e1 * inv;
    d_a[ij * 3 + 2] = e2 * inv;
}

// ---------------- fused LBP iteration (unchanged) ----------------
__global__ void __launch_bounds__(320) lbp_fused(
    const float* __restrict__ mb_src, float* __restrict__ mb_dst,
    const float* __restrict__ stot_src, float* __restrict__ stot_dst,
    float* __restrict__ stot_zero)
{
    const int tid = threadIdx.x;
    const int w = tid >> 5, lane = tid & 31;
    const int b = blockIdx.x;
    const int j = b % M_;
    const int i = (b / M_) * 10 + w;
    __shared__ float tt[10][32];
    __shared__ float sred[10][32];

    if (b < 12) {
        int z = b * 320 + tid;
        if (z < M_ * C_) stot_zero[z] = 0.f;
    }

    if (lane < C_)
        tt[w][lane] = d_psi[i * C_ + lane] + stot_src[i * C_ + lane]
                    - mb_src[(j * M_ + i) * C_ + lane];
    __syncwarp();

    const float* ph = d_phi + (size_t)(i * C_) * MC + j * C_;
    float mv = -1e30f;
    if (lane < C_) {
        #pragma unroll 6
        for (int p = 0; p < C_; p++)
            mv = fmaxf(mv, tt[w][p] + ph[(size_t)p * MC + lane]);
        mv = fmaxf(mv, 0.f);
    }
    float mx = (lane < C_) ? mv : -1e30f;
    #pragma unroll
    for (int o = 16; o; o >>= 1) mx = fmaxf(mx, __shfl_xor_sync(0xffffffffu, mx, o));
    float e = (lane < C_) ? __expf(mv - mx) : 0.f;
    float sum = e;
    #pragma unroll
    for (int o = 16; o; o >>= 1) sum += __shfl_xor_sync(0xffffffffu, sum, o);

    float newm = 0.f;
    if (lane < C_) {
        float sm = e / sum;
        float old = mb_src[(i * M_ + j) * C_ + lane];
        newm = __logf(0.5f * __expf(old) + 0.5f * sm);
        mb_dst[(i * M_ + j) * C_ + lane] = newm;
    }
    sred[w][lane] = newm;
    __syncthreads();

    if (tid < C_) {
        float s = 0.f;
        #pragma unroll
        for (int w2 = 0; w2 < 10; w2++) s += sred[w2][tid];
        atomicAdd(&stot_dst[j * C_ + tid], s);
    }
}

__global__ void final_kernel(float* __restrict__ out, const float* __restrict__ mbar,
                             const float* __restrict__ stot)
{
    int i = blockIdx.x;
    int lane = threadIdx.x;
    float u = -1e30f;
    if (lane < C_)
        u = d_psi[i * C_ + lane] + stot[i * C_ + lane]
          - mbar[(i * M_ + i) * C_ + lane];
    float mx = u;
    #pragma unroll
    for (int o = 16; o; o >>= 1) mx = fmaxf(mx, __shfl_xor_sync(0xffffffffu, mx, o));
    float e = (lane < C_) ? expf(u - mx) : 0.f;
    float sum = e;
    #pragma unroll
    for (int o = 16; o; o >>= 1) sum += __shfl_xor_sync(0xffffffffu, sum, o);
    if (lane < C_) out[i * C_ + lane] = e / sum;
}

// ---------------- host ----------------
extern "C" void kernel_launch(void* const* d_in, const int* in_sizes, int n_in,
                              void* d_out, int out_size)
{
    const float* ent    = (const float*)d_in[0];
    const float* fmc_in = (const float*)d_in[1];
    const float* W_fmc  = (const float*)d_in[2];
    const float* b_fmc  = (const float*)d_in[3];
    const float* Bmat   = (const float*)d_in[4];
    const float* Rmat   = (const float*)d_in[5];
    const float* Dmat   = (const float*)d_in[6];
    float* out = (float*)d_out;

    float *pf, *pg, *pfD, *ps, *pmA, *pmB, *pS, *pBt;
    cudaGetSymbolAddress((void**)&pf,  d_f);
    cudaGetSymbolAddress((void**)&pg,  d_g);
    cudaGetSymbolAddress((void**)&pfD, d_fD);
    cudaGetSymbolAddress((void**)&ps,  d_s);
    cudaGetSymbolAddress((void**)&pmA, d_mbarA);
    cudaGetSymbolAddress((void**)&pmB, d_mbarB);
    cudaGetSymbolAddress((void**)&pS,  d_S);
    cudaGetSymbolAddress((void**)&pBt, d_Bt);
    float* S[3] = { pS, pS + M_*C_, pS + 2*M_*C_ };

    cudaFuncSetAttribute(er_mma,  cudaFuncAttributeMaxDynamicSharedMemorySize, 2 * ER_BUF * 4);
    cudaFuncSetAttribute(phi_mma, cudaFuncAttributeMaxDynamicSharedMemorySize, 2 * PHI_BUF * 4);

    // all zeroing + operand packing in one launch
    mega_pack<<<592, 256>>>(ent, Rmat, Bmat);

    // f = tanh(fmc_in @ W_fmc + b): split-K 8 (KC=128; last split partial)
    gemm_nn_ca<<<dim3(5, 2, 8), 256>>>(fmc_in, W_fmc, nullptr, pf, nullptr,
                                       100, 300, 900, 128, 8, 0, 0);
    ftanh<<<(M_ * D_ + 255) / 256, 256>>>(b_fmc);
    // batched: g = f @ Bt (NN, batch 0) + fD_k = f @ D_k (batches 1..3), split-K 3
    gemm_nn_ca<<<dim3(5, 2, 12), 256>>>(pf, pBt, Dmat, pg, pfD,
                                        100, 300, 300, 112, 3, 90000, 30000);
    // s_k = fD_k @ f^T: batch 3 x split-K 3
    gemm_nt_ca<<<dim3(2, 2, 9), 256>>>(pfD, pf, ps, 100, 100, 300, 112, 3,
                                       30000, 10000);
    psi_kernel<<<100, 256>>>(ent);
    a_kernel<<<40, 256>>>();

    // tensor-core GEMMs
    er_mma<<<dim3(5, 24, 3), 256, 2 * ER_BUF * 4>>>();
    phi_mma<<<dim3(47, 24), 256, 2 * PHI_BUF * 4>>>();

    // fused LBP: 10 damped iterations; mbar ping-pong A<->B, stot rotates S0/S1/S2
    for (int it = 0; it < 10; it++) {
        const float* msrc = (it & 1) ? pmB : pmA;
        float*       mdst = (it & 1) ? pmA : pmB;
        lbp_fused<<<1000, 320>>>(msrc, mdst,
                                 S[it % 3], S[(it + 1) % 3], S[(it + 2) % 3]);
    }
    final_kernel<<<100, 32>>>(out, pmA, S[1]);
}